// round 16
// baseline (speedup 1.0000x reference)
#include <cuda_runtime.h>

// image [8,512,512,32] f32, slic [8,512,512,1] i32 in [1,256]
// out [8,256,32] f32 = segment_sum(image) / segment_count_nonzero(image) per channel.
//
// Streaming v3. Key insight from R4/R15 fits: __launch_bounds__(1024,2)
// capped regs at 32 -> MLP~1 -> latency-bound at ~4TB/s (66us floor).
// Fix: 256-thread blocks @ ~51 regs, batch 4 (label,image) loads in
// registers before the atomic rounds; store per-block partials coalesced
// (no REDG flush tail); reduce partials in a lean finalize.

#define BATCH 8
#define HW    (512*512)
#define C     32
#define S     256
#define CS    33                    // skew: bank = (s + 4*sub + k) mod 32
#define BPI   92                    // blocks per image; 736 total = ~5/SM
#define NBLK  (BATCH * BPI)
#define THREADS 256
#define WSTRIDE (BPI * 8 * 4)       // 2944: per-warp 4-pixel-group stride

__device__ float g_part[NBLK * S * C];   // 24MB per-block partials (overwritten)
__device__ float g_pixp[NBLK * S];       // per-block pixel counts  (overwritten)
__device__ float g_zero[BATCH * S * C];  // exact-zero corrections (rare; self-cleaned)

// ---------------------------------------------------------------------------
// seg_accum: warp = 4 consecutive pixels, thread = channel quad (LDG.128,
// 512B contiguous/warp). Batch 4 groups: 4 int4 label broadcasts + 4 float4
// image loads issued back-to-back (MLP 8/warp), then 4 atomic rounds into
// the skewed smem accumulator. Block ends with a coalesced partial store.
// ---------------------------------------------------------------------------
__global__ void __launch_bounds__(THREADS, 5)
seg_accum(const float* __restrict__ img, const int* __restrict__ slic) {
    __shared__ float s_sum[S * CS];   // 33.8KB skewed
    __shared__ float s_pix[S];

    const int b    = blockIdx.y;
    const int blk  = blockIdx.x;
    const int t    = threadIdx.x;
    const int warp = t >> 5;
    const int lane = t & 31;
    const int q    = lane >> 3;       // pixel within the group
    const int sub  = lane & 7;        // channel quad

    for (int i = t; i < S * CS; i += THREADS) s_sum[i] = 0.0f;
    if (t < S) s_pix[t] = 0.0f;
    __syncthreads();

    const float* __restrict__ imgb  = img  + (size_t)b * HW * C;
    const int*   __restrict__ slicb = slic + (size_t)b * HW;
    float* __restrict__ gzb = g_zero + (size_t)b * S * C;

    const int base = (blk * 8 + warp) * 4;

    for (int p0 = base; p0 < HW; p0 += 4 * WSTRIDE) {
        int4   lab[4];
        float4 v[4];
        #pragma unroll
        for (int u = 0; u < 4; u++) {
            const int p = p0 + u * WSTRIDE;
            if (p < HW) {
                lab[u] = *(const int4*)(slicb + p);                    // broadcast, 1 wf
                v[u]   = *(const float4*)(imgb + (size_t)(p + q) * C + sub * 4);
            }
        }
        #pragma unroll
        for (int u = 0; u < 4; u++) {
            const int p = p0 + u * WSTRIDE;
            if (p < HW) {
                const int4 L = lab[u];
                const int  s = (q == 0 ? L.x : q == 1 ? L.y : q == 2 ? L.z : L.w) - 1;
                const int  sb = s * CS + sub * 4;
                const float4 w = v[u];
                atomicAdd(&s_sum[sb + 0], w.x);
                atomicAdd(&s_sum[sb + 1], w.y);
                atomicAdd(&s_sum[sb + 2], w.z);
                atomicAdd(&s_sum[sb + 3], w.w);
                if (lane < 4) {       // 1 instr / 4 pixels
                    const int sq = (lane == 0 ? L.x : lane == 1 ? L.y :
                                    lane == 2 ? L.z : L.w) - 1;
                    atomicAdd(&s_pix[sq], 1.0f);
                }
                // Exact count_nonzero: predicated, never taken for gaussian data.
                const int gb = s * C + sub * 4;
                if (w.x == 0.0f) atomicAdd(&gzb[gb + 0], 1.0f);
                if (w.y == 0.0f) atomicAdd(&gzb[gb + 1], 1.0f);
                if (w.z == 0.0f) atomicAdd(&gzb[gb + 2], 1.0f);
                if (w.w == 0.0f) atomicAdd(&gzb[gb + 3], 1.0f);
            }
        }
    }
    __syncthreads();

    // Coalesced partial store (de-skew): 8 STG.128 per thread, no atomics.
    float* __restrict__ gp = g_part + (size_t)(b * BPI + blk) * S * C;
    for (int i4 = t; i4 < (S * C) / 4; i4 += THREADS) {
        const int i = i4 * 4, s = i >> 5, c = i & 31;
        float4 o;
        o.x = s_sum[s * CS + c    ];
        o.y = s_sum[s * CS + c + 1];
        o.z = s_sum[s * CS + c + 2];
        o.w = s_sum[s * CS + c + 3];
        ((float4*)gp)[i4] = o;
    }
    if (t < S) g_pixp[(b * BPI + blk) * S + t] = s_pix[t];
}

// ---------------------------------------------------------------------------
// finalize: out[i] = (sum over 92 partials) / (pix - zeros). Coalesced
// strided loads, unroll 4 for MLP; self-cleans g_zero for the next replay.
// ---------------------------------------------------------------------------
__global__ void finalize(float* __restrict__ out) {
    const int i = blockIdx.x * 256 + threadIdx.x;    // 65536 threads
    if (i >= BATCH * S * C) return;
    const int b  = i >> 13;
    const int sc = i & 8191;
    const int s  = sc >> 5;

    const float* __restrict__ gp = g_part + (size_t)b * BPI * (S * C) + sc;
    const float* __restrict__ gx = g_pixp + b * BPI * S + s;

    float sum = 0.0f, pix = 0.0f;
    #pragma unroll 4
    for (int k = 0; k < BPI; k++) {
        sum += gp[(size_t)k * (S * C)];   // coalesced across the warp
        pix += gx[k * S];                 // broadcast line
    }
    out[i] = sum / (pix - g_zero[i]);
    g_zero[i] = 0.0f;                     // restore invariant for next replay
}

// ---------------------------------------------------------------------------
// Entry point (graph-capturable: two kernel launches, no sync, no alloc).
// ---------------------------------------------------------------------------
extern "C" void kernel_launch(void* const* d_in, const int* in_sizes, int n_in,
                              void* d_out, int out_size) {
    const float* img  = (const float*)d_in[0];   // image, 67108864 f32
    const int*   slic = (const int*)  d_in[1];   // slic,   2097152 i32
    float*       out  = (float*)d_out;           // 65536 f32

    (void)in_sizes; (void)n_in; (void)out_size;

    dim3 grid(BPI, BATCH);
    seg_accum<<<grid, THREADS>>>(img, slic);

    finalize<<<(BATCH * S * C + 255) / 256, 256>>>(out);
}

// round 17
// speedup vs baseline: 1.2531x; 1.2531x over previous
#include <cuda_runtime.h>

// image [8,512,512,32] f32, slic [8,512,512,1] i32 in [1,256]
// out [8,256,32] f32 = segment_sum(image) / segment_count_nonzero(image) per channel.
//
// Streaming v4. Root cause across R4/R5/R15/R16: register ceilings
// (launch_bounds 1024,2 -> 32 regs) prevented load batching -> MLP~1 ->
// load-LATENCY bound at ~4TB/s. Fix: 512 threads @ 64 regs, lane=channel
// (one 128B wavefront per pixel), 8 scalar loads batched per inner step,
// conflict-free skewed smem atomics, no bounds checks in the hot loop.

#define BATCH 8
#define HW    (512*512)
#define C     32
#define S     256
#define CS    33                  // skew: bank = (s + lane) mod 32, all distinct
#define BPI   37                  // 296 blocks = 2 per SM
#define THREADS 512               // 16 warps
#define CHUNKS  (HW / 32)         // 8192 32-pixel chunks per image
#define CSTRIDE (BPI * 16)        // 592 warp-slots per image sweep

// Scratch (zero at module load; finalize self-cleans every call).
__device__ float g_sums[BATCH * S * C];
__device__ float g_zero[BATCH * S * C];   // exact-zero corrections (rare path)
__device__ float g_pix [BATCH * S];

__global__ void __launch_bounds__(THREADS, 2)
seg_accum(const float* __restrict__ img, const int* __restrict__ slic) {
    __shared__ float s_sum[S * CS];   // 33.8KB skewed accumulator
    __shared__ float s_pix[S];

    const int b    = blockIdx.y;
    const int warp = threadIdx.x >> 5;
    const int lane = threadIdx.x & 31;

    for (int i = threadIdx.x; i < S * CS; i += THREADS) s_sum[i] = 0.0f;
    if (threadIdx.x < S) s_pix[threadIdx.x] = 0.0f;
    __syncthreads();

    const float* __restrict__ imgb  = img  + (size_t)b * HW * C;
    const int*   __restrict__ slicb = slic + (size_t)b * HW;
    float* __restrict__ gzb = g_zero + (size_t)b * S * C;

    // Warp processes 32 consecutive pixels per chunk; HW % 32 == 0 so the
    // hot loop has NO bounds checks (batching stays unguarded).
    for (int c = blockIdx.x * 16 + warp; c < CHUNKS; c += CSTRIDE) {
        const int p0 = c * 32;

        // Pixel counts: one coalesced label line + one full-lane ATOMS
        // per 32 pixels (0.06 wf/px). Random banks -> minor phasing only.
        const int myl = slicb[p0 + lane] - 1;
        atomicAdd(&s_pix[myl], 1.0f);

        #pragma unroll
        for (int g = 0; g < 4; g++) {            // 4 sub-groups of 8 pixels
            const int pb = p0 + g * 8;

            // Batch phase: 2 broadcast label quads + 8 independent 128B
            // image lines issued back-to-back (MLP 8/warp).
            const int4 La = *(const int4*)(slicb + pb);
            const int4 Lb = *(const int4*)(slicb + pb + 4);
            float v[8];
            #pragma unroll
            for (int u = 0; u < 8; u++)
                v[u] = imgb[(size_t)(pb + u) * C + lane];   // 1 wf each

            // Drain phase: 8 conflict-free ATOMS rounds (banks (s+lane)%32).
            #pragma unroll
            for (int u = 0; u < 8; u++) {
                const int4 L = (u < 4) ? La : Lb;
                const int  k = u & 3;
                const int  s = (k == 0 ? L.x : k == 1 ? L.y :
                                k == 2 ? L.z : L.w) - 1;
                atomicAdd(&s_sum[s * CS + lane], v[u]);
                // Exact count_nonzero: predicated, never taken for gaussian.
                if (v[u] == 0.0f) atomicAdd(&gzb[s * C + lane], 1.0f);
            }
        }
    }
    __syncthreads();

    // Flush block-private accumulators (de-skew): 296 x 8448 spread REDG
    // lanes over 65K addresses (~38 ops/addr) — cheap, no-return.
    float* __restrict__ gs = g_sums + (size_t)b * S * C;
    for (int i = threadIdx.x; i < S * C; i += THREADS)
        atomicAdd(&gs[i], s_sum[(i >> 5) * CS + (i & 31)]);
    if (threadIdx.x < S)
        atomicAdd(&g_pix[b * S + threadIdx.x], s_pix[threadIdx.x]);
}

// ---------------------------------------------------------------------------
// out = sum / (pixel_count - zero_count); self-clean scratch for next replay.
// (g_pix hazard confined to one warp: warp-wide load precedes lane-0 store.)
// ---------------------------------------------------------------------------
__global__ void finalize(float* __restrict__ out) {
    int i = blockIdx.x * blockDim.x + threadIdx.x;
    if (i < BATCH * S * C) {
        float cnt = g_pix[i >> 5] - g_zero[i];
        out[i] = g_sums[i] / cnt;
        g_sums[i] = 0.0f;
        g_zero[i] = 0.0f;
        if ((i & 31) == 0) g_pix[i >> 5] = 0.0f;
    }
}

// ---------------------------------------------------------------------------
// Entry point (graph-capturable: two kernel launches, no sync, no alloc).
// ---------------------------------------------------------------------------
extern "C" void kernel_launch(void* const* d_in, const int* in_sizes, int n_in,
                              void* d_out, int out_size) {
    const float* img  = (const float*)d_in[0];   // image, 67108864 f32
    const int*   slic = (const int*)  d_in[1];   // slic,   2097152 i32
    float*       out  = (float*)d_out;           // 65536 f32

    (void)in_sizes; (void)n_in; (void)out_size;

    dim3 grid(BPI, BATCH);
    seg_accum<<<grid, THREADS>>>(img, slic);

    finalize<<<(BATCH * S * C + 255) / 256, 256>>>(out);
}